// round 1
// baseline (speedup 1.0000x reference)
#include <cuda_runtime.h>
#include <math.h>

#ifndef M_PI
#define M_PI 3.14159265358979323846
#endif

#define NIMG 124
#define NSIDE 128
#define NPIX (NSIDE*NSIDE)
#define NTOT (NIMG*NPIX)
#define LAM_C 0.1f

// ---- scratch state (no cudaMalloc allowed) ----
__device__ float g_X[NTOT];
__device__ float g_G1[NTOT];
__device__ float g_G21[NTOT];
__device__ float g_G22[NTOT];
__device__ float g_DhZ[NTOT];
__device__ float g_DvZ[NTOT];
__device__ float g_Uh[NTOT];
__device__ float g_Uv[NTOT];
__device__ float g_R[NTOT];
__device__ float g_T1[NTOT];
__device__ float g_T2[NTOT];
__device__ float g_Z[NTOT];
__device__ float g_Q[NSIDE*NSIDE];   // real orthogonal trig basis
__device__ float g_lam[NSIDE];       // eigenvalues of 1D circular Laplacian

// ======================= init: Q matrix + eigenvalues =======================
__global__ void init_q_kernel() {
    int r = blockIdx.x;      // 0..127
    int n = threadIdx.x;     // 0..127
    double inv = 1.0 / 128.0;
    double s1 = sqrt(inv), s2 = sqrt(2.0 * inv);
    float v;
    if (r == 0)        v = (float)s1;
    else if (r < 64)   v = (float)(s2 * cos(2.0 * M_PI * (double)r * (double)n * inv));
    else if (r == 64)  v = (n & 1) ? (float)(-s1) : (float)s1;
    else               v = (float)(s2 * sin(2.0 * M_PI * (double)(r - 64) * (double)n * inv));
    g_Q[r * NSIDE + n] = v;
    if (n == 0) {
        int f = (r <= 64) ? r : (r - 64);
        g_lam[r] = (float)(2.0 - 2.0 * cos(2.0 * M_PI * (double)f * inv));
    }
}

// ======================= init state =======================
__global__ void init_state_kernel(const float* __restrict__ Y) {
    int idx = blockIdx.x * blockDim.x + threadIdx.x;
    if (idx >= NTOT) return;
    int p = idx & (NPIX - 1);
    int base = idx - p;
    int i = p >> 7, j = p & 127;
    int jm = (j - 1) & 127, im = (i - 1) & 127;
    float y = Y[idx];
    g_X[idx] = y;
    g_G1[idx] = 0.f; g_G21[idx] = 0.f; g_G22[idx] = 0.f;
    g_DhZ[idx] = y - Y[base + (i << 7) + jm];
    g_DvZ[idx] = y - Y[base + (im << 7) + j];
}

__device__ __forceinline__ float shrinkf(float x, float t) {
    return copysignf(fmaxf(fabsf(x) - t, 0.f), x);
}

// ======================= pre: Uh, Uv, R =======================
// R = mu1*X + G1 + DhT(mu2*Uh+G21) + DvT(mu2*Uv+G22)
// DhT(u)[i,j] = u[i,j] - u[i,j+1];  DvT(u)[i,j] = u[i,j] - u[i+1,j]
__global__ void pre_kernel(float mu1, float mu2) {
    int idx = blockIdx.x * blockDim.x + threadIdx.x;
    if (idx >= NTOT) return;
    int p = idx & (NPIX - 1);
    int base = idx - p;
    int i = p >> 7, j = p & 127;
    int jp = (j + 1) & 127, ip = (i + 1) & 127;
    int idr = base + (i << 7) + jp;   // right neighbor
    int idd = base + (ip << 7) + j;   // down neighbor
    float inv2 = 1.f / mu2;
    float thr = LAM_C * inv2;

    float g21c = g_G21[idx], g22c = g_G22[idx];
    float uh = shrinkf(g_DhZ[idx] - g21c * inv2, thr);
    float uv = shrinkf(g_DvZ[idx] - g22c * inv2, thr);
    g_Uh[idx] = uh;
    g_Uv[idx] = uv;
    float Ph_c = mu2 * uh + g21c;
    float Pv_c = mu2 * uv + g22c;

    float g21r = g_G21[idr];
    float uh_r = shrinkf(g_DhZ[idr] - g21r * inv2, thr);
    float Ph_r = mu2 * uh_r + g21r;

    float g22d = g_G22[idd];
    float uv_d = shrinkf(g_DvZ[idd] - g22d * inv2, thr);
    float Pv_d = mu2 * uv_d + g22d;

    g_R[idx] = mu1 * g_X[idx] + g_G1[idx] + (Ph_c - Ph_r) + (Pv_c - Pv_d);
}

// ======================= post: DhZ/DvZ/X/G updates =======================
__global__ void post_kernel(const float* __restrict__ Y, const float* __restrict__ inW,
                            float mu1, float mu2) {
    int idx = blockIdx.x * blockDim.x + threadIdx.x;
    if (idx >= NTOT) return;
    int p = idx & (NPIX - 1);
    int base = idx - p;
    int i = p >> 7, j = p & 127;
    int jm = (j - 1) & 127, im = (i - 1) & 127;
    float z = g_Z[idx];
    float dh = z - g_Z[base + (i << 7) + jm];
    float dv = z - g_Z[base + (im << 7) + j];
    g_DhZ[idx] = dh;
    g_DvZ[idx] = dv;
    float w = inW[idx], y = Y[idx], g1 = g_G1[idx];
    float x = (w * y + mu1 * z - g1) / (w + mu1);
    g_X[idx] = x;
    g_G1[idx] = g1 + mu1 * (x - z);
    g_G21[idx] += mu2 * (g_Uh[idx] - dh);
    g_G22[idx] += mu2 * (g_Uv[idx] - dv);
}

// ======================= batched 128x128x128 GEMM =======================
// MODE 0: C[b] = Q    * A[b]
// MODE 1: C[b] = (A[b] * Q^T) ⊙ D,  D[r][c] = 1/(mu1+mu2*(lam[r]+lam[c]))
// MODE 2: C[b] = Q^T  * A[b]
// MODE 3: C[b] = A[b] * Q
// block (16,16); each thread computes a 4x4 micro-tile; 64x64 output tile per block
template<int MODE>
__global__ void __launch_bounds__(256)
gemm_kernel(const float* __restrict__ A, float* __restrict__ C,
            float mu1, float mu2) {
    __shared__ float Ls[16][64];   // Ls[k][m]
    __shared__ float Rs[16][64];   // Rs[k][n]
    int b = blockIdx.z;
    const float* Ab = A + (size_t)b * NPIX;
    float* Cb = C + (size_t)b * NPIX;
    int tM = blockIdx.y * 64, tN = blockIdx.x * 64;
    int tx = threadIdx.x, ty = threadIdx.y;
    int tid = ty * 16 + tx;

    float acc[4][4] = {};

    for (int k0 = 0; k0 < 128; k0 += 16) {
        // ---- load L operand into Ls[k][m] ----
        if (MODE == 1 || MODE == 3) {
            // L = A[b], row-major: float4 row load, scatter to smem
            int m = tid >> 2, kq = tid & 3;
            float4 v = *(const float4*)&Ab[(tM + m) * 128 + k0 + kq * 4];
            Ls[kq * 4 + 0][m] = v.x;
            Ls[kq * 4 + 1][m] = v.y;
            Ls[kq * 4 + 2][m] = v.z;
            Ls[kq * 4 + 3][m] = v.w;
        } else {
            #pragma unroll
            for (int l = 0; l < 4; l++) {
                int ii = tid + l * 256;
                int k = ii >> 6, m = ii & 63;
                float v;
                if (MODE == 0) v = g_Q[(tM + m) * 128 + (k0 + k)];   // Q
                else           v = g_Q[(k0 + k) * 128 + (tM + m)];   // Q^T
                Ls[k][m] = v;
            }
        }
        // ---- load R operand into Rs[k][n] ----
        #pragma unroll
        for (int l = 0; l < 4; l++) {
            int ii = tid + l * 256;
            int k = ii >> 6, n = ii & 63;
            float w;
            if (MODE == 0 || MODE == 2) w = Ab[(k0 + k) * 128 + (tN + n)];   // A
            else if (MODE == 1)         w = g_Q[(tN + n) * 128 + (k0 + k)];  // Q^T
            else                        w = g_Q[(k0 + k) * 128 + (tN + n)];  // Q
            Rs[k][n] = w;
        }
        __syncthreads();

        #pragma unroll
        for (int kk = 0; kk < 16; kk++) {
            float4 av = *(const float4*)&Ls[kk][ty * 4];
            float4 bv = *(const float4*)&Rs[kk][tx * 4];
            float a0 = av.x, a1 = av.y, a2 = av.z, a3 = av.w;
            float b0 = bv.x, b1 = bv.y, b2 = bv.z, b3 = bv.w;
            acc[0][0] += a0 * b0; acc[0][1] += a0 * b1; acc[0][2] += a0 * b2; acc[0][3] += a0 * b3;
            acc[1][0] += a1 * b0; acc[1][1] += a1 * b1; acc[1][2] += a1 * b2; acc[1][3] += a1 * b3;
            acc[2][0] += a2 * b0; acc[2][1] += a2 * b1; acc[2][2] += a2 * b2; acc[2][3] += a2 * b3;
            acc[3][0] += a3 * b0; acc[3][1] += a3 * b1; acc[3][2] += a3 * b2; acc[3][3] += a3 * b3;
        }
        __syncthreads();
    }

    // ---- epilogue (float4 stores; MODE 1 applies the spectral filter) ----
    #pragma unroll
    for (int iiy = 0; iiy < 4; iiy++) {
        int r = tM + ty * 4 + iiy;
        float4 v;
        v.x = acc[iiy][0]; v.y = acc[iiy][1]; v.z = acc[iiy][2]; v.w = acc[iiy][3];
        if (MODE == 1) {
            float lr = g_lam[r];
            int c = tN + tx * 4;
            v.x *= 1.f / (mu1 + mu2 * (lr + g_lam[c + 0]));
            v.y *= 1.f / (mu1 + mu2 * (lr + g_lam[c + 1]));
            v.z *= 1.f / (mu1 + mu2 * (lr + g_lam[c + 2]));
            v.w *= 1.f / (mu1 + mu2 * (lr + g_lam[c + 3]));
        }
        *(float4*)&Cb[r * 128 + tN + tx * 4] = v;
    }
}

// ======================= launcher =======================
extern "C" void kernel_launch(void* const* d_in, const int* in_sizes, int n_in,
                              void* d_out, int out_size) {
    const float* Y   = (const float*)d_in[0];
    const float* inW = (const float*)d_in[1];
    float* out = (float*)d_out;

    float *pR, *pT1, *pT2, *pZ;
    cudaGetSymbolAddress((void**)&pR,  g_R);
    cudaGetSymbolAddress((void**)&pT1, g_T1);
    cudaGetSymbolAddress((void**)&pT2, g_T2);
    cudaGetSymbolAddress((void**)&pZ,  g_Z);

    init_q_kernel<<<128, 128>>>();
    const int EB = 256;
    const int EG = (NTOT + EB - 1) / EB;
    init_state_kernel<<<EG, EB>>>(Y);

    dim3 gb(2, 2, NIMG), tb(16, 16);
    double m1 = 0.1, m2 = 0.1;
    for (int t = 0; t < 20; t++) {
        float mu1 = (float)m1, mu2 = (float)m2;
        pre_kernel<<<EG, EB>>>(mu1, mu2);
        gemm_kernel<0><<<gb, tb>>>(pR,  pT1, mu1, mu2);                 // T1 = Q R
        gemm_kernel<1><<<gb, tb>>>(pT1, pT2, mu1, mu2);                 // T2 = (T1 Q^T) ⊙ D
        gemm_kernel<2><<<gb, tb>>>(pT2, pT1, mu1, mu2);                 // T1 = Q^T T2
        float* zdst = (t == 19) ? out : pZ;
        gemm_kernel<3><<<gb, tb>>>(pT1, zdst, mu1, mu2);                // Z = T1 Q
        if (t < 19) post_kernel<<<EG, EB>>>(Y, inW, mu1, mu2);
        m1 *= 1.05; m2 *= 1.05;
    }
}

// round 2
// speedup vs baseline: 1.1518x; 1.1518x over previous
#include <cuda_runtime.h>
#include <math.h>

#ifndef M_PI
#define M_PI 3.14159265358979323846
#endif

#define NIMG 124
#define NSIDE 128
#define NPIX (NSIDE*NSIDE)
#define NTOT (NIMG*NPIX)
#define LAM_C 0.1f
#define SPAD 130                    // smem row stride in floats (even + bank-skewed)

typedef unsigned long long ull;

// ---- persistent state (no cudaMalloc allowed) ----
__device__ float g_X[NTOT], g_G1[NTOT], g_G21[NTOT], g_G22[NTOT];
__device__ float g_DhZ[NTOT], g_DvZ[NTOT], g_Uh[NTOT], g_Uv[NTOT];
__device__ float g_Q[NPIX];      // real orthogonal trig eigenbasis, row-major
__device__ float g_Qt[NPIX];     // its transpose
__device__ float g_lam[NSIDE];   // eigenvalues of 1D circular Laplacian

// ======================= init: Q, Q^T, eigenvalues =======================
__global__ void init_q_kernel() {
    int r = blockIdx.x;      // 0..127
    int n = threadIdx.x;     // 0..127
    double inv = 1.0 / 128.0;
    double s1 = sqrt(inv), s2 = sqrt(2.0 * inv);
    float v;
    if (r == 0)        v = (float)s1;
    else if (r < 64)   v = (float)(s2 * cos(2.0 * M_PI * (double)r * (double)n * inv));
    else if (r == 64)  v = (n & 1) ? (float)(-s1) : (float)s1;
    else               v = (float)(s2 * sin(2.0 * M_PI * (double)(r - 64) * (double)n * inv));
    g_Q[r * NSIDE + n]  = v;
    g_Qt[n * NSIDE + r] = v;
    if (n == 0) {
        int f = (r <= 64) ? r : (r - 64);
        g_lam[r] = (float)(2.0 - 2.0 * cos(2.0 * M_PI * (double)f * inv));
    }
}

__device__ __forceinline__ float shrinkf(float x, float t) {
    return copysignf(fmaxf(fabsf(x) - t, 0.f), x);
}

// packed fp32x2 helpers (Blackwell FFMA2)
__device__ __forceinline__ ull pack2(float x) {
    ull r; asm("mov.b64 %0, {%1, %1};" : "=l"(r) : "f"(x)); return r;
}
__device__ __forceinline__ void ffma2(ull& d, ull a, ull b) {
    asm("fma.rn.f32x2 %0, %1, %2, %0;" : "+l"(d) : "l"(a), "l"(b));
}

// ============ one 128x128x128 GEMM stage, in shared memory, may alias C with L or R ============
// C[m][n] = sum_k L[m][k] * R[k][n]   (optionally * spectral filter)
// thread (tx,ty) of a 16x16 grid owns rows 8*ty..8*ty+7, col pairs {32*jp + 2*tx}, jp=0..3
template<bool FILT>
__device__ __forceinline__ void gemm_stage(const float* __restrict__ Lb,
                                           const float* __restrict__ Rb,
                                           float* __restrict__ Cb,
                                           const float* __restrict__ lam,
                                           float mu1, float mu2, int tx, int ty) {
    ull acc[8][4];
#pragma unroll
    for (int i = 0; i < 8; i++)
#pragma unroll
        for (int jp = 0; jp < 4; jp++) acc[i][jp] = 0ull;

    const float* lrow = Lb + (8 * ty) * SPAD;
    const float* rcol = Rb + 2 * tx;

#pragma unroll 8
    for (int k = 0; k < 128; k++) {
        ull b[4];
#pragma unroll
        for (int jp = 0; jp < 4; jp++)
            b[jp] = *(const ull*)(rcol + k * SPAD + 32 * jp);
#pragma unroll
        for (int i = 0; i < 8; i++) {
            ull a2 = pack2(lrow[i * SPAD + k]);
#pragma unroll
            for (int jp = 0; jp < 4; jp++) ffma2(acc[i][jp], a2, b[jp]);
        }
    }
    __syncthreads();   // all reads of the (possibly aliased) buffer complete before any write

#pragma unroll
    for (int i = 0; i < 8; i++) {
        int r = 8 * ty + i;
#pragma unroll
        for (int jp = 0; jp < 4; jp++) {
            int c = 32 * jp + 2 * tx;
            float2 v = *reinterpret_cast<float2*>(&acc[i][jp]);
            if (FILT) {
                float lr = lam[r];
                v.x *= 1.f / (mu1 + mu2 * (lr + lam[c]));
                v.y *= 1.f / (mu1 + mu2 * (lr + lam[c + 1]));
            }
            *reinterpret_cast<float2*>(&Cb[r * SPAD + c]) = v;
        }
    }
    __syncthreads();   // stores visible before next stage reads
}

// ======================= fused whole-problem kernel: 1 CTA per image =======================
extern __shared__ float smem[];

__global__ void __launch_bounds__(256, 1)
hwtv_fused(const float* __restrict__ Y, const float* __restrict__ inW,
           float* __restrict__ out) {
    float* sQ   = smem;
    float* sQt  = smem + 128 * SPAD;
    float* sT   = smem + 2 * 128 * SPAD;
    float* sLam = smem + 3 * 128 * SPAD;

    int tid = threadIdx.x;
    int tx = tid & 15, ty = tid >> 4;
    int b = blockIdx.x;
    int base = b * NPIX;

    // stage Q / Q^T / lam into smem (padded layout)
    for (int p = tid; p < NPIX; p += 256) {
        int r = p >> 7, c = p & 127;
        sQ[r * SPAD + c]  = g_Q[p];
        sQt[r * SPAD + c] = g_Qt[p];
    }
    if (tid < 128) sLam[tid] = g_lam[tid];

    // init ADMM state for this image
    for (int p = tid; p < NPIX; p += 256) {
        int i = p >> 7, j = p & 127;
        int idx = base + p;
        float y = Y[idx];
        g_X[idx] = y;
        g_G1[idx] = 0.f; g_G21[idx] = 0.f; g_G22[idx] = 0.f;
        g_DhZ[idx] = y - Y[base + (i << 7) + ((j - 1) & 127)];
        g_DvZ[idx] = y - Y[base + (((i - 1) & 127) << 7) + j];
    }
    __syncthreads();

    double m1d = 0.1, m2d = 0.1;
    for (int t = 0; t < 20; t++) {
        float mu1 = (float)m1d, mu2 = (float)m2d;
        float inv2 = 1.f / mu2, thr = LAM_C * inv2;

        // ---- pre: shrink + build RHS directly into smem ----
        // R = mu1*X + G1 + DhT(mu2*Uh+G21) + DvT(mu2*Uv+G22)
        for (int p = tid; p < NPIX; p += 256) {
            int i = p >> 7, j = p & 127;
            int idx = base + p;
            int idr = base + (i << 7) + ((j + 1) & 127);
            int idd = base + (((i + 1) & 127) << 7) + j;

            float g21c = g_G21[idx], g22c = g_G22[idx];
            float uh = shrinkf(g_DhZ[idx] - g21c * inv2, thr);
            float uv = shrinkf(g_DvZ[idx] - g22c * inv2, thr);
            g_Uh[idx] = uh; g_Uv[idx] = uv;
            float Ph_c = mu2 * uh + g21c;
            float Pv_c = mu2 * uv + g22c;

            float g21r = g_G21[idr];
            float Ph_r = mu2 * shrinkf(g_DhZ[idr] - g21r * inv2, thr) + g21r;
            float g22d = g_G22[idd];
            float Pv_d = mu2 * shrinkf(g_DvZ[idd] - g22d * inv2, thr) + g22d;

            sT[i * SPAD + j] = mu1 * g_X[idx] + g_G1[idx] + (Ph_c - Ph_r) + (Pv_c - Pv_d);
        }
        __syncthreads();

        // ---- spectral solve: Z = Q^T [ (Q R Q^T) ⊙ D ] Q, all in-place in sT ----
        gemm_stage<false>(sQ,  sT,  sT, sLam, mu1, mu2, tx, ty);   // T = Q * R
        gemm_stage<true >(sT,  sQt, sT, sLam, mu1, mu2, tx, ty);   // T = (T * Q^T) ⊙ D
        gemm_stage<false>(sQt, sT,  sT, sLam, mu1, mu2, tx, ty);   // T = Q^T * T
        gemm_stage<false>(sT,  sQ,  sT, sLam, mu1, mu2, tx, ty);   // T = T * Q  (= Z)

        if (t == 19) {
            for (int p = tid; p < NPIX; p += 256)
                out[base + p] = sT[(p >> 7) * SPAD + (p & 127)];
        } else {
            // ---- post: gradients of Z (from smem) + X/G updates ----
            for (int p = tid; p < NPIX; p += 256) {
                int i = p >> 7, j = p & 127;
                int idx = base + p;
                float z = sT[i * SPAD + j];
                float dh = z - sT[i * SPAD + ((j - 1) & 127)];
                float dv = z - sT[((i - 1) & 127) * SPAD + j];
                g_DhZ[idx] = dh; g_DvZ[idx] = dv;
                float w = inW[idx], y = Y[idx], g1 = g_G1[idx];
                float x = (w * y + mu1 * z - g1) / (w + mu1);
                g_X[idx] = x;
                g_G1[idx] = g1 + mu1 * (x - z);
                g_G21[idx] += mu2 * (g_Uh[idx] - dh);
                g_G22[idx] += mu2 * (g_Uv[idx] - dv);
            }
            __syncthreads();
        }
        m1d *= 1.05; m2d *= 1.05;
    }
}

// ======================= launcher =======================
extern "C" void kernel_launch(void* const* d_in, const int* in_sizes, int n_in,
                              void* d_out, int out_size) {
    const float* Y   = (const float*)d_in[0];
    const float* inW = (const float*)d_in[1];
    float* out = (float*)d_out;

    const int smem_bytes = (3 * 128 * SPAD + 128) * (int)sizeof(float);  // 200,192 B
    static int configured = 0;
    cudaFuncSetAttribute(hwtv_fused, cudaFuncAttributeMaxDynamicSharedMemorySize, smem_bytes);
    (void)configured;

    init_q_kernel<<<128, 128>>>();
    hwtv_fused<<<NIMG, 256, smem_bytes>>>(Y, inW, out);
}

// round 3
// speedup vs baseline: 1.5865x; 1.3774x over previous
#include <cuda_runtime.h>
#include <math.h>

#ifndef M_PI
#define M_PI 3.14159265358979323846
#endif

#define NIMG 124
#define NSIDE 128
#define NPIX (NSIDE*NSIDE)
#define NTOT (NIMG*NPIX)
#define LAM_C 0.1f
#define SPAD 130                    // smem row stride in floats
#define NTHR 512

typedef unsigned long long ull;

// ---- persistent state (no cudaMalloc allowed) ----
__device__ float g_X[NTOT], g_G1[NTOT], g_G21[NTOT], g_G22[NTOT];
__device__ float g_DhZ[NTOT], g_DvZ[NTOT], g_Uh[NTOT], g_Uv[NTOT];
__device__ float g_Q[NPIX];      // real orthogonal trig eigenbasis, row-major
__device__ float g_Qt[NPIX];     // its transpose
__device__ float g_lam[NSIDE];   // eigenvalues of 1D circular Laplacian

// ======================= init: Q, Q^T, eigenvalues =======================
__global__ void init_q_kernel() {
    int r = blockIdx.x;      // 0..127
    int n = threadIdx.x;     // 0..127
    double inv = 1.0 / 128.0;
    double s1 = sqrt(inv), s2 = sqrt(2.0 * inv);
    float v;
    if (r == 0)        v = (float)s1;
    else if (r < 64)   v = (float)(s2 * cos(2.0 * M_PI * (double)r * (double)n * inv));
    else if (r == 64)  v = (n & 1) ? (float)(-s1) : (float)s1;
    else               v = (float)(s2 * sin(2.0 * M_PI * (double)(r - 64) * (double)n * inv));
    g_Q[r * NSIDE + n]  = v;
    g_Qt[n * NSIDE + r] = v;
    if (n == 0) {
        int f = (r <= 64) ? r : (r - 64);
        g_lam[r] = (float)(2.0 - 2.0 * cos(2.0 * M_PI * (double)f * inv));
    }
}

__device__ __forceinline__ float shrinkf(float x, float t) {
    return copysignf(fmaxf(fabsf(x) - t, 0.f), x);
}

// packed fp32x2 helpers (Blackwell FFMA2)
__device__ __forceinline__ ull pack2(float x) {
    ull r; asm("mov.b64 %0, {%1, %1};" : "=l"(r) : "f"(x)); return r;
}
__device__ __forceinline__ void ffma2(ull& d, ull a, ull b) {
    asm("fma.rn.f32x2 %0, %1, %2, %0;" : "+l"(d) : "l"(a), "l"(b));
}

// ============ one 128x128x128 GEMM stage in shared memory; C may alias L or R ============
// C[m][n] = sum_k L[m][k] * R[k][n]   (optionally * spectral filter)
// 512 threads as (tx 0..15, ty 0..31): rows m = 4*ty+i (i<4), cols c = 2*tx + 32*jp (jp<4)
template<bool FILT>
__device__ __forceinline__ void gemm_stage(const float* __restrict__ Lb,
                                           const float* __restrict__ Rb,
                                           float* __restrict__ Cb,
                                           const float* __restrict__ lam,
                                           float mu1, float mu2, int tx, int ty) {
    ull acc[4][4];
#pragma unroll
    for (int i = 0; i < 4; i++)
#pragma unroll
        for (int jp = 0; jp < 4; jp++) acc[i][jp] = 0ull;

    const float* lrow = Lb + (4 * ty) * SPAD;
    const float* rcol = Rb + 2 * tx;

#pragma unroll 4
    for (int k = 0; k < 128; k += 2) {
        ull b0[4], b1[4];
#pragma unroll
        for (int jp = 0; jp < 4; jp++) {
            b0[jp] = *(const ull*)(rcol + k * SPAD + 32 * jp);
            b1[jp] = *(const ull*)(rcol + (k + 1) * SPAD + 32 * jp);
        }
#pragma unroll
        for (int i = 0; i < 4; i++) {
            float2 ap = *(const float2*)(lrow + i * SPAD + k);
            ull a0 = pack2(ap.x), a1 = pack2(ap.y);
#pragma unroll
            for (int jp = 0; jp < 4; jp++) ffma2(acc[i][jp], a0, b0[jp]);
#pragma unroll
            for (int jp = 0; jp < 4; jp++) ffma2(acc[i][jp], a1, b1[jp]);
        }
    }
    __syncthreads();   // all reads of the (possibly aliased) buffer complete before any write

#pragma unroll
    for (int i = 0; i < 4; i++) {
        int r = 4 * ty + i;
#pragma unroll
        for (int jp = 0; jp < 4; jp++) {
            int c = 32 * jp + 2 * tx;
            float2 v = *reinterpret_cast<float2*>(&acc[i][jp]);
            if (FILT) {
                float lr = lam[r];
                v.x *= 1.f / (mu1 + mu2 * (lr + lam[c]));
                v.y *= 1.f / (mu1 + mu2 * (lr + lam[c + 1]));
            }
            *reinterpret_cast<float2*>(&Cb[r * SPAD + c]) = v;
        }
    }
    __syncthreads();   // stores visible before next stage reads
}

// ======================= fused whole-problem kernel: 1 CTA per image =======================
extern __shared__ float smem[];

__global__ void __launch_bounds__(NTHR, 1)
hwtv_fused(const float* __restrict__ Y, const float* __restrict__ inW,
           float* __restrict__ out) {
    float* sQ   = smem;
    float* sQt  = smem + 128 * SPAD;
    float* sT   = smem + 2 * 128 * SPAD;
    float* sLam = smem + 3 * 128 * SPAD;

    int tid = threadIdx.x;
    int tx = tid & 15, ty = tid >> 4;
    int b = blockIdx.x;
    int base = b * NPIX;

    // stage Q / Q^T / lam into smem (padded layout)
    for (int p = tid; p < NPIX; p += NTHR) {
        int r = p >> 7, c = p & 127;
        sQ[r * SPAD + c]  = g_Q[p];
        sQt[r * SPAD + c] = g_Qt[p];
    }
    if (tid < 128) sLam[tid] = g_lam[tid];

    // init ADMM state for this image
    for (int p = tid; p < NPIX; p += NTHR) {
        int i = p >> 7, j = p & 127;
        int idx = base + p;
        float y = Y[idx];
        g_X[idx] = y;
        g_G1[idx] = 0.f; g_G21[idx] = 0.f; g_G22[idx] = 0.f;
        g_DhZ[idx] = y - Y[base + (i << 7) + ((j - 1) & 127)];
        g_DvZ[idx] = y - Y[base + (((i - 1) & 127) << 7) + j];
    }
    __syncthreads();

    double m1d = 0.1, m2d = 0.1;
    for (int t = 0; t < 20; t++) {
        float mu1 = (float)m1d, mu2 = (float)m2d;
        float inv2 = 1.f / mu2, thr = LAM_C * inv2;

        // ---- pre: shrink + build RHS directly into smem ----
        // R = mu1*X + G1 + DhT(mu2*Uh+G21) + DvT(mu2*Uv+G22)
        for (int p = tid; p < NPIX; p += NTHR) {
            int i = p >> 7, j = p & 127;
            int idx = base + p;
            int idr = base + (i << 7) + ((j + 1) & 127);
            int idd = base + (((i + 1) & 127) << 7) + j;

            float g21c = g_G21[idx], g22c = g_G22[idx];
            float uh = shrinkf(g_DhZ[idx] - g21c * inv2, thr);
            float uv = shrinkf(g_DvZ[idx] - g22c * inv2, thr);
            g_Uh[idx] = uh; g_Uv[idx] = uv;
            float Ph_c = mu2 * uh + g21c;
            float Pv_c = mu2 * uv + g22c;

            float g21r = g_G21[idr];
            float Ph_r = mu2 * shrinkf(g_DhZ[idr] - g21r * inv2, thr) + g21r;
            float g22d = g_G22[idd];
            float Pv_d = mu2 * shrinkf(g_DvZ[idd] - g22d * inv2, thr) + g22d;

            sT[i * SPAD + j] = mu1 * g_X[idx] + g_G1[idx] + (Ph_c - Ph_r) + (Pv_c - Pv_d);
        }
        __syncthreads();

        // ---- spectral solve: Z = Q^T [ (Q R Q^T) ⊙ D ] Q, all in-place in sT ----
        gemm_stage<false>(sQ,  sT,  sT, sLam, mu1, mu2, tx, ty);   // T = Q * R
        gemm_stage<true >(sT,  sQt, sT, sLam, mu1, mu2, tx, ty);   // T = (T * Q^T) ⊙ D
        gemm_stage<false>(sQt, sT,  sT, sLam, mu1, mu2, tx, ty);   // T = Q^T * T
        gemm_stage<false>(sT,  sQ,  sT, sLam, mu1, mu2, tx, ty);   // T = T * Q  (= Z)

        if (t == 19) {
            for (int p = tid; p < NPIX; p += NTHR)
                out[base + p] = sT[(p >> 7) * SPAD + (p & 127)];
        } else {
            // ---- post: gradients of Z (from smem) + X/G updates ----
            for (int p = tid; p < NPIX; p += NTHR) {
                int i = p >> 7, j = p & 127;
                int idx = base + p;
                float z = sT[i * SPAD + j];
                float dh = z - sT[i * SPAD + ((j - 1) & 127)];
                float dv = z - sT[((i - 1) & 127) * SPAD + j];
                g_DhZ[idx] = dh; g_DvZ[idx] = dv;
                float w = inW[idx], y = Y[idx], g1 = g_G1[idx];
                float x = (w * y + mu1 * z - g1) / (w + mu1);
                g_X[idx] = x;
                g_G1[idx] = g1 + mu1 * (x - z);
                g_G21[idx] += mu2 * (g_Uh[idx] - dh);
                g_G22[idx] += mu2 * (g_Uv[idx] - dv);
            }
            __syncthreads();
        }
        m1d *= 1.05; m2d *= 1.05;
    }
}

// ======================= launcher =======================
extern "C" void kernel_launch(void* const* d_in, const int* in_sizes, int n_in,
                              void* d_out, int out_size) {
    const float* Y   = (const float*)d_in[0];
    const float* inW = (const float*)d_in[1];
    float* out = (float*)d_out;

    const int smem_bytes = (3 * 128 * SPAD + 128) * (int)sizeof(float);  // 200,192 B
    cudaFuncSetAttribute(hwtv_fused, cudaFuncAttributeMaxDynamicSharedMemorySize, smem_bytes);

    init_q_kernel<<<128, 128>>>();
    hwtv_fused<<<NIMG, NTHR, smem_bytes>>>(Y, inW, out);
}

// round 5
// speedup vs baseline: 2.2984x; 1.4488x over previous
#include <cuda_runtime.h>
#include <math.h>

#ifndef M_PI
#define M_PI 3.14159265358979323846
#endif

#define NIMG 124
#define NSIDE 128
#define NPIX (NSIDE*NSIDE)
#define NTOT (NIMG*NPIX)
#define LAM_C 0.1f
#define SPAD 132                    // smem row stride in floats (16B-aligned rows, 4-bank skew)
#define NTHR 512

typedef unsigned long long ull;

// ---- persistent state (no cudaMalloc allowed) ----
__device__ float g_X[NTOT], g_G1[NTOT], g_G21[NTOT], g_G22[NTOT];
__device__ float g_DhZ[NTOT], g_DvZ[NTOT];
__device__ float g_Q[NPIX];      // real orthogonal trig eigenbasis, row-major
__device__ float g_Qt[NPIX];     // its transpose
__device__ float g_lam[NSIDE];   // eigenvalues of 1D circular Laplacian

// ======================= init: Q, Q^T, eigenvalues =======================
__global__ void init_q_kernel() {
    int r = blockIdx.x, n = threadIdx.x;
    double inv = 1.0 / 128.0;
    double s1 = sqrt(inv), s2 = sqrt(2.0 * inv);
    float v;
    if (r == 0)        v = (float)s1;
    else if (r < 64)   v = (float)(s2 * cos(2.0 * M_PI * (double)r * (double)n * inv));
    else if (r == 64)  v = (n & 1) ? (float)(-s1) : (float)s1;
    else               v = (float)(s2 * sin(2.0 * M_PI * (double)(r - 64) * (double)n * inv));
    g_Q[r * NSIDE + n]  = v;
    g_Qt[n * NSIDE + r] = v;
    if (n == 0) {
        int f = (r <= 64) ? r : (r - 64);
        g_lam[r] = (float)(2.0 - 2.0 * cos(2.0 * M_PI * (double)f * inv));
    }
}

__device__ __forceinline__ float shrinkf(float x, float t) {
    return copysignf(fmaxf(fabsf(x) - t, 0.f), x);
}

// packed fp32x2 helpers (Blackwell FFMA2)
__device__ __forceinline__ ull pack2(float x) {
    ull r; asm("mov.b64 %0, {%1, %1};" : "=l"(r) : "f"(x)); return r;
}
__device__ __forceinline__ void ffma2(ull& d, ull a, ull b) {
    asm("fma.rn.f32x2 %0, %1, %2, %0;" : "+l"(d) : "l"(a), "l"(b));
}

// ---- GEMM load/compute helpers (register double-buffering) ----
struct KPair { ull b[8]; float2 a[4]; };

__device__ __forceinline__ void load_kpair(KPair& P, const float* rcol, const float* lrow, int k) {
#pragma unroll
    for (int jp = 0; jp < 4; jp++) {
        P.b[jp]     = *(const ull*)(rcol + k * SPAD + 32 * jp);
        P.b[4 + jp] = *(const ull*)(rcol + (k + 1) * SPAD + 32 * jp);
    }
#pragma unroll
    for (int i = 0; i < 4; i++) P.a[i] = *(const float2*)(lrow + i * SPAD + k);
}

__device__ __forceinline__ void comp_kpair(ull acc[4][4], const KPair& P) {
#pragma unroll
    for (int i = 0; i < 4; i++) {
        ull a0 = pack2(P.a[i].x), a1 = pack2(P.a[i].y);
#pragma unroll
        for (int jp = 0; jp < 4; jp++) ffma2(acc[i][jp], a0, P.b[jp]);
#pragma unroll
        for (int jp = 0; jp < 4; jp++) ffma2(acc[i][jp], a1, P.b[4 + jp]);
    }
}

// ============ one 128x128x128 GEMM stage in shared memory; C may alias L or R ============
// C[m][n] = sum_k L[m][k] * R[k][n]   (optionally * spectral filter)
// 512 threads as (tx 0..15, ty 0..31): rows m = 4*ty+i (i<4), cols c = 2*tx + 32*jp (jp<4)
template<bool FILT>
__device__ __forceinline__ void gemm_stage(const float* __restrict__ Lb,
                                           const float* __restrict__ Rb,
                                           float* __restrict__ Cb,
                                           const float* __restrict__ lam,
                                           float mu1, float mu2, int tx, int ty) {
    ull acc[4][4];
#pragma unroll
    for (int i = 0; i < 4; i++)
#pragma unroll
        for (int jp = 0; jp < 4; jp++) acc[i][jp] = 0ull;

    const float* lrow = Lb + (4 * ty) * SPAD;
    const float* rcol = Rb + 2 * tx;

    KPair E, O;
    load_kpair(E, rcol, lrow, 0);
#pragma unroll 2
    for (int kp = 0; kp < 64; kp += 2) {
        load_kpair(O, rcol, lrow, 2 * kp + 2);      // prefetch odd (max k = 126)
        comp_kpair(acc, E);
        if (kp + 2 < 64) load_kpair(E, rcol, lrow, 2 * kp + 4);  // prefetch next even
        comp_kpair(acc, O);
    }
    __syncthreads();   // all reads of the (possibly aliased) buffer complete before any write

#pragma unroll
    for (int i = 0; i < 4; i++) {
        int r = 4 * ty + i;
#pragma unroll
        for (int jp = 0; jp < 4; jp++) {
            int c = 32 * jp + 2 * tx;
            float2 v = *reinterpret_cast<float2*>(&acc[i][jp]);
            if (FILT) {
                float lr = lam[r];
                v.x *= 1.f / (mu1 + mu2 * (lr + lam[c]));
                v.y *= 1.f / (mu1 + mu2 * (lr + lam[c + 1]));
            }
            *reinterpret_cast<float2*>(&Cb[r * SPAD + c]) = v;
        }
    }
    __syncthreads();   // stores visible before next stage reads
}

// ---- float4 helpers ----
__device__ __forceinline__ float4 ld4(const float* p) { return *(const float4*)p; }
__device__ __forceinline__ void st4(float* p, float4 v) { *(float4*)p = v; }

// ======================= fused whole-problem kernel: 1 CTA per image =======================
extern __shared__ float smem[];

__global__ void __launch_bounds__(NTHR, 1)
hwtv_fused(const float* __restrict__ Y, const float* __restrict__ inW,
           float* __restrict__ out) {
    float* sQ   = smem;
    float* sQt  = smem + 128 * SPAD;
    float* sT   = smem + 2 * 128 * SPAD;
    float* sLam = smem + 3 * 128 * SPAD;

    int tid = threadIdx.x;
    int tx = tid & 15, ty = tid >> 4;
    int base = blockIdx.x * NPIX;

    // stage Q / Q^T / lam into smem (padded layout)
    for (int p = tid; p < NPIX; p += NTHR) {
        int r = p >> 7, c = p & 127;
        sQ[r * SPAD + c]  = g_Q[p];
        sQt[r * SPAD + c] = g_Qt[p];
    }
    if (tid < 128) sLam[tid] = g_lam[tid];

    // init ADMM state for this image
    for (int p = tid; p < NPIX; p += NTHR) {
        int i = p >> 7, j = p & 127;
        int idx = base + p;
        float y = Y[idx];
        g_X[idx] = y;
        g_G1[idx] = 0.f; g_G21[idx] = 0.f; g_G22[idx] = 0.f;
        g_DhZ[idx] = y - Y[base + (i << 7) + ((j - 1) & 127)];
        g_DvZ[idx] = y - Y[base + (((i - 1) & 127) << 7) + j];
    }
    __syncthreads();

    double m1d = 0.1, m2d = 0.1;
    for (int t = 0; t < 20; t++) {
        float mu1 = (float)m1d, mu2 = (float)m2d;
        float inv2 = 1.f / mu2, thr = LAM_C * inv2;

        // ---- pre: shrink + build RHS directly into smem (4 px per step) ----
        // R = mu1*X + G1 + DhT(mu2*Uh+G21) + DvT(mu2*Uv+G22)
        for (int ch = tid; ch < NPIX / 4; ch += NTHR) {
            int i = ch >> 5, c0 = (ch & 31) * 4;
            int idx = base + (i << 7) + c0;

            float4 dh = ld4(&g_DhZ[idx]), dv = ld4(&g_DvZ[idx]);
            float4 g21 = ld4(&g_G21[idx]), g22 = ld4(&g_G22[idx]);
            float4 x4 = ld4(&g_X[idx]),  g1 = ld4(&g_G1[idx]);

            float4 Ph, Pv;
            Ph.x = mu2 * shrinkf(dh.x - g21.x * inv2, thr) + g21.x;
            Ph.y = mu2 * shrinkf(dh.y - g21.y * inv2, thr) + g21.y;
            Ph.z = mu2 * shrinkf(dh.z - g21.z * inv2, thr) + g21.z;
            Ph.w = mu2 * shrinkf(dh.w - g21.w * inv2, thr) + g21.w;
            Pv.x = mu2 * shrinkf(dv.x - g22.x * inv2, thr) + g22.x;
            Pv.y = mu2 * shrinkf(dv.y - g22.y * inv2, thr) + g22.y;
            Pv.z = mu2 * shrinkf(dv.z - g22.z * inv2, thr) + g22.z;
            Pv.w = mu2 * shrinkf(dv.w - g22.w * inv2, thr) + g22.w;

            // right neighbor of Ph: element at col c0+4
            int jr = (c0 + 4) & 127;
            int idr = base + (i << 7) + jr;
            float dh_r = g_DhZ[idr], g21_r = g_G21[idr];
            float Ph4 = mu2 * shrinkf(dh_r - g21_r * inv2, thr) + g21_r;

            // down neighbor row for Pv
            int idd = base + (((i + 1) & 127) << 7) + c0;
            float4 dv_d = ld4(&g_DvZ[idd]), g22_d = ld4(&g_G22[idd]);
            float4 Pvd;
            Pvd.x = mu2 * shrinkf(dv_d.x - g22_d.x * inv2, thr) + g22_d.x;
            Pvd.y = mu2 * shrinkf(dv_d.y - g22_d.y * inv2, thr) + g22_d.y;
            Pvd.z = mu2 * shrinkf(dv_d.z - g22_d.z * inv2, thr) + g22_d.z;
            Pvd.w = mu2 * shrinkf(dv_d.w - g22_d.w * inv2, thr) + g22_d.w;

            float4 R;
            R.x = mu1 * x4.x + g1.x + (Ph.x - Ph.y) + (Pv.x - Pvd.x);
            R.y = mu1 * x4.y + g1.y + (Ph.y - Ph.z) + (Pv.y - Pvd.y);
            R.z = mu1 * x4.z + g1.z + (Ph.z - Ph.w) + (Pv.z - Pvd.z);
            R.w = mu1 * x4.w + g1.w + (Ph.w - Ph4)  + (Pv.w - Pvd.w);
            st4(&sT[i * SPAD + c0], R);
        }
        __syncthreads();

        // ---- spectral solve: Z = Q^T [ (Q R Q^T) ⊙ D ] Q, all in-place in sT ----
        gemm_stage<false>(sQ,  sT,  sT, sLam, mu1, mu2, tx, ty);   // T = Q * R
        gemm_stage<true >(sT,  sQt, sT, sLam, mu1, mu2, tx, ty);   // T = (T * Q^T) ⊙ D
        gemm_stage<false>(sQt, sT,  sT, sLam, mu1, mu2, tx, ty);   // T = Q^T * T
        gemm_stage<false>(sT,  sQ,  sT, sLam, mu1, mu2, tx, ty);   // T = T * Q  (= Z)

        if (t == 19) {
            for (int ch = tid; ch < NPIX / 4; ch += NTHR) {
                int i = ch >> 5, c0 = (ch & 31) * 4;
                st4(&out[base + (i << 7) + c0], ld4(&sT[i * SPAD + c0]));
            }
        } else {
            // ---- post: gradients of Z (smem) + X/G updates; Uh/Uv recomputed ----
            for (int ch = tid; ch < NPIX / 4; ch += NTHR) {
                int i = ch >> 5, c0 = (ch & 31) * 4;
                int idx = base + (i << 7) + c0;

                float4 z = ld4(&sT[i * SPAD + c0]);
                float zl = sT[i * SPAD + ((c0 - 1) & 127)];
                float4 zu = ld4(&sT[((i - 1) & 127) * SPAD + c0]);
                float4 dh, dv;
                dh.x = z.x - zl;  dh.y = z.y - z.x;  dh.z = z.z - z.y;  dh.w = z.w - z.z;
                dv.x = z.x - zu.x; dv.y = z.y - zu.y; dv.z = z.z - zu.z; dv.w = z.w - zu.w;

                float4 dho = ld4(&g_DhZ[idx]), dvo = ld4(&g_DvZ[idx]);
                float4 g21 = ld4(&g_G21[idx]), g22 = ld4(&g_G22[idx]);
                float4 g1 = ld4(&g_G1[idx]);
                float4 w = ld4(&inW[idx]), y = ld4(&Y[idx]);

                // recompute Uh/Uv from pre-iteration state (bit-identical to pre's values)
                float4 uh, uv;
                uh.x = shrinkf(dho.x - g21.x * inv2, thr); uh.y = shrinkf(dho.y - g21.y * inv2, thr);
                uh.z = shrinkf(dho.z - g21.z * inv2, thr); uh.w = shrinkf(dho.w - g21.w * inv2, thr);
                uv.x = shrinkf(dvo.x - g22.x * inv2, thr); uv.y = shrinkf(dvo.y - g22.y * inv2, thr);
                uv.z = shrinkf(dvo.z - g22.z * inv2, thr); uv.w = shrinkf(dvo.w - g22.w * inv2, thr);

                float4 x, g1n, g21n, g22n;
                x.x = (w.x * y.x + mu1 * z.x - g1.x) / (w.x + mu1);
                x.y = (w.y * y.y + mu1 * z.y - g1.y) / (w.y + mu1);
                x.z = (w.z * y.z + mu1 * z.z - g1.z) / (w.z + mu1);
                x.w = (w.w * y.w + mu1 * z.w - g1.w) / (w.w + mu1);
                g1n.x = g1.x + mu1 * (x.x - z.x); g1n.y = g1.y + mu1 * (x.y - z.y);
                g1n.z = g1.z + mu1 * (x.z - z.z); g1n.w = g1.w + mu1 * (x.w - z.w);
                g21n.x = g21.x + mu2 * (uh.x - dh.x); g21n.y = g21.y + mu2 * (uh.y - dh.y);
                g21n.z = g21.z + mu2 * (uh.z - dh.z); g21n.w = g21.w + mu2 * (uh.w - dh.w);
                g22n.x = g22.x + mu2 * (uv.x - dv.x); g22n.y = g22.y + mu2 * (uv.y - dv.y);
                g22n.z = g22.z + mu2 * (uv.z - dv.z); g22n.w = g22.w + mu2 * (uv.w - dv.w);

                st4(&g_DhZ[idx], dh); st4(&g_DvZ[idx], dv);
                st4(&g_X[idx], x);    st4(&g_G1[idx], g1n);
                st4(&g_G21[idx], g21n); st4(&g_G22[idx], g22n);
            }
            __syncthreads();
        }
        m1d *= 1.05; m2d *= 1.05;
    }
}

// ======================= launcher =======================
extern "C" void kernel_launch(void* const* d_in, const int* in_sizes, int n_in,
                              void* d_out, int out_size) {
    const float* Y   = (const float*)d_in[0];
    const float* inW = (const float*)d_in[1];
    float* out = (float*)d_out;

    const int smem_bytes = (3 * 128 * SPAD + 128) * (int)sizeof(float);  // 203,264 B
    cudaFuncSetAttribute(hwtv_fused, cudaFuncAttributeMaxDynamicSharedMemorySize, smem_bytes);

    init_q_kernel<<<128, 128>>>();
    hwtv_fused<<<NIMG, NTHR, smem_bytes>>>(Y, inW, out);
}